// round 4
// baseline (speedup 1.0000x reference)
#include <cuda_runtime.h>
#include <cuda_bf16.h>

#define TT    512
#define BN    8192
#define NTOT  (TT * BN)          // 4,194,304
#define S     8                  // timesteps per chunk
#define NC    (TT / S)           // 64 chunks
#define BLK   256
#define JB    (BN / BLK)         // 32 block-columns
#define GRD   (NC * JB)          // 2048 blocks

#define GAMMA_F 0.99f

// Scratch (device globals; allocation-free)
__device__ float g_aggA[NC * BN];    // 2 MB: chunk affine A per element
__device__ float g_aggB[NC * BN];    // 2 MB: chunk affine B per element
__device__ int   g_flag[GRD];        // 8 KB: per-block "agg published"
__device__ float g_part[2 * GRD];    // block partials: actor | critic
__device__ unsigned int g_ctr;

// ---------------------------------------------------------------------------
// Tiny reset: clear flags + completion counter (graph-replay safe).
// ---------------------------------------------------------------------------
__global__ void __launch_bounds__(BLK)
reset_k()
{
    const int i = blockIdx.x * BLK + threadIdx.x;
    if (i < GRD) g_flag[i] = 0;
    if (i == 0)  g_ctr = 0;
}

// ---------------------------------------------------------------------------
// Fused single-pass V-trace + PPO loss.
//   Block (c, j): chunk c (time [c*S, c*S+S)), batch elems [j*256, j*256+256).
//   blockIdx maps chunk NC-1 -> lowest bx so every wait targets a lower bx.
// ---------------------------------------------------------------------------
__global__ void __launch_bounds__(BLK)
fused(const float2* __restrict__ prob,    // [T,B] pairs (A=2)
      const float2* __restrict__ aprob,
      const float*  __restrict__ v,
      const float*  __restrict__ rew,
      const int*    __restrict__ act,
      const int*    __restrict__ dn,
      const float*  __restrict__ nv,
      float*        __restrict__ out)
{
    const int bx = blockIdx.x;
    const int cr = bx >> 5;            // 0..NC-1 (0 = latest chunk)
    const int c  = NC - 1 - cr;        // chunk index
    const int j  = bx & (JB - 1);
    const int b  = (j << 8) + threadIdx.x;
    const int tTop = c * S + S - 1;

    // ---- Phase A: stream inputs once; build chunk affine; buffer replay data
    float ratB[S], vB[S], rB[S];       // registers
    float Aagg = 1.0f, Bagg = 0.0f;

    #pragma unroll
    for (int i = 0; i < S; i++) {
        const int t   = tTop - i;      // descending time
        const int idx = t * BN + b;

        const float2 p  = __ldcs(&prob[idx]);
        const float2 ap = __ldcs(&aprob[idx]);
        const float  vv = __ldcs(&v[idx]);
        const float  rr = __ldcs(&rew[idx]);
        const int    a  = __ldcs(&act[idx]);
        const int    d  = __ldcs(&dn[idx]);

        const float pa   = a ? p.y  : p.x;
        const float apa  = a ? ap.y : ap.x;
        const float rat  = __fdividef(pa * (ap.x + ap.y), (p.x + p.y) * apa);
        const float g    = d ? 0.0f : GAMMA_F;
        const float rho  = fminf(rat, 1.0f);
        const float At   = rho * g;
        const float Bt   = fmaf(rho, rr - vv, vv);

        Aagg = At * Aagg;              // compose step_t o F
        Bagg = fmaf(At, Bagg, Bt);

        ratB[i] = __uint_as_float(__float_as_uint(rat) | ((unsigned)d << 31));
        vB[i]   = vv;
        rB[i]   = rr;
    }

    // ---- Publish chunk aggregate (release)
    if (c > 0) {                                   // chunk 0 has no consumer
        g_aggA[c * BN + b] = Aagg;
        g_aggB[c * BN + b] = Bagg;
        __threadfence();
        __syncthreads();
        if (threadIdx.x == 0)
            ((volatile int*)g_flag)[bx] = 1;
    }

    // ---- Phase B: entry carry via deterministic fixed-order aggregate fold
    float E;
    if (c == NC - 1) {
        E = __ldg(&nv[(TT - 1) * BN + b]);
    } else {
        // Wait until all later chunks (same j) have published.
        if (threadIdx.x == 0) {
            for (int cc = c + 1; cc < NC; cc++) {
                const int slot = (NC - 1 - cc) * JB + j;
                while (((volatile int*)g_flag)[slot] == 0) __nanosleep(64);
            }
        }
        __syncthreads();
        __threadfence();   // acquire: order agg loads after flag observation

        // Fold aggregates cc = c+1 .. NC-1 in fixed order (deterministic).
        float la = 1.0f, lb = 0.0f;
        for (int cc = c + 1; cc < NC; cc++) {
            const float A1 = g_aggA[cc * BN + b];
            const float B1 = g_aggB[cc * BN + b];
            lb = fmaf(la, B1, lb);
            la = la * A1;
        }
        E = fmaf(la, __ldg(&nv[(TT - 1) * BN + b]), lb);
    }

    // ---- Replay from registers; accumulate losses
    float actor = 0.0f, critic = 0.0f;
    #pragma unroll
    for (int i = 0; i < S; i++) {
        const unsigned u = __float_as_uint(ratB[i]);
        const float ratio = __uint_as_float(u & 0x7fffffffu);
        const float g    = (u >> 31) ? 0.0f : GAMMA_F;
        const float rho  = fminf(ratio, 1.0f);
        const float adv  = rho * (rB[i] + g * E - vB[i]);
        critic = fmaf(adv, adv, critic);
        const float cl = fminf(fmaxf(ratio, 0.8f), 1.2f);
        actor += fminf(ratio * adv, cl * adv);
        E = vB[i] + adv;
    }

    // ---- Block reduction (deterministic)
    __shared__ float sa[8], sc[8];
    #pragma unroll
    for (int o = 16; o > 0; o >>= 1) {
        actor  += __shfl_down_sync(0xffffffffu, actor,  o);
        critic += __shfl_down_sync(0xffffffffu, critic, o);
    }
    const int w = threadIdx.x >> 5;
    if ((threadIdx.x & 31) == 0) { sa[w] = actor; sc[w] = critic; }
    __syncthreads();
    if (threadIdx.x == 0) {
        float A = 0.0f, C = 0.0f;
        #pragma unroll
        for (int k = 0; k < 8; k++) { A += sa[k]; C += sc[k]; }
        g_part[bx]       = A;
        g_part[GRD + bx] = C;
    }

    // ---- Last block: final deterministic reduction
    __shared__ bool is_last;
    if (threadIdx.x == 0) {
        __threadfence();
        is_last = (atomicAdd(&g_ctr, 1u) == (unsigned)(GRD - 1));
    }
    __syncthreads();
    if (is_last) {
        const int t = threadIdx.x;
        __shared__ float ra[BLK], rc[BLK];
        float A = 0.0f, C = 0.0f;
        #pragma unroll
        for (int k = 0; k < GRD / BLK; k++) {     // fixed order
            A += g_part[t + k * BLK];
            C += g_part[GRD + t + k * BLK];
        }
        ra[t] = A; rc[t] = C;
        __syncthreads();
        #pragma unroll
        for (int s = BLK / 2; s > 0; s >>= 1) {
            if (t < s) { ra[t] += ra[t + s]; rc[t] += rc[t + s]; }
            __syncthreads();
        }
        if (t == 0) {
            const float inv = 1.0f / (float)NTOT;
            out[0] = (-ra[0] + 0.5f * rc[0]) * inv;
        }
    }
}

extern "C" void kernel_launch(void* const* d_in, const int* in_sizes, int n_in,
                              void* d_out, int out_size)
{
    const float2* prob  = (const float2*)d_in[0];
    const float2* aprob = (const float2*)d_in[1];
    const float*  v     = (const float*)d_in[2];
    const float*  nv    = (const float*)d_in[3];
    const float*  rew   = (const float*)d_in[4];
    const int*    act   = (const int*)d_in[5];
    const int*    dn    = (const int*)d_in[6];
    float* out = (float*)d_out;

    reset_k<<<(GRD + BLK - 1) / BLK, BLK>>>();
    fused<<<GRD, BLK>>>(prob, aprob, v, rew, act, dn, nv, out);
}

// round 5
// speedup vs baseline: 2.2472x; 2.2472x over previous
#include <cuda_runtime.h>
#include <cuda_bf16.h>

#define TT    512
#define BN    8192
#define NTOT  (TT * BN)         // 4,194,304
#define NC    32                // time chunks
#define S     (TT / NC)         // 16 steps per chunk
#define BLK   256
#define JB    (BN / BLK)        // 32 block-columns
#define GRD   (NC * JB)         // 1024 blocks

#define GAMMA_F 0.99f

// Scratch (device globals: allocation-free)
__device__ float g_ratio[NTOT];      // |ratio| with done bit in sign
__device__ float g_Ac[NC * BN];      // chunk affine A
__device__ float g_Bc[NC * BN];      // chunk affine B
__device__ float g_part[2 * GRD];    // block partials: actor | critic
__device__ unsigned int g_ctr;

// ---------------------------------------------------------------------------
// Pass 1: per-element ratio (done bit in sign) + chunk affine (A,B).
//   carry_t = A_t*carry_{t+1} + B_t ;  A_t = rho*g ,  B_t = v + rho*(r - v)
// One thread = one batch element, one time chunk. Streaming inputs use
// __ldcs so v/rew/ratio stay L2-warm for pass3.
// ---------------------------------------------------------------------------
__global__ void __launch_bounds__(BLK)
pass1(const float2* __restrict__ prob,
      const float2* __restrict__ aprob,
      const float*  __restrict__ v,
      const float*  __restrict__ rew,
      const int*    __restrict__ act,
      const int*    __restrict__ dn)
{
    if (blockIdx.x == 0 && threadIdx.x == 0) g_ctr = 0;   // for pass3 finish

    const int c  = blockIdx.x >> 5;                       // chunk
    const int b  = ((blockIdx.x & 31) << 8) + threadIdx.x;
    const int t1 = c * S + S - 1;

    float Aagg = 1.0f, Bagg = 0.0f;

    #pragma unroll
    for (int i = 0; i < S; i++) {
        const int t   = t1 - i;                 // descending time
        const int idx = t * BN + b;

        const float2 p  = __ldcs(&prob[idx]);
        const float2 ap = __ldcs(&aprob[idx]);
        const int    a  = __ldcs(&act[idx]);
        const int    d  = __ldcs(&dn[idx]);
        const float  vv = __ldg(&v[idx]);
        const float  rr = __ldg(&rew[idx]);

        const float pa   = a ? p.y  : p.x;
        const float apa  = a ? ap.y : ap.x;
        const float rat  = __fdividef(pa * (ap.x + ap.y), (p.x + p.y) * apa);
        const float g    = d ? 0.0f : GAMMA_F;
        const float rho  = fminf(rat, 1.0f);
        const float At   = rho * g;
        const float Bt   = fmaf(rho, rr - vv, vv);

        Aagg = At * Aagg;                       // compose step_t o F
        Bagg = fmaf(At, Bagg, Bt);

        g_ratio[idx] =
            __uint_as_float(__float_as_uint(rat) | ((unsigned)d << 31));
    }

    g_Ac[c * BN + b] = Aagg;
    g_Bc[c * BN + b] = Bagg;
}

// ---------------------------------------------------------------------------
// Pass 3 (fused entry-carry fold + replay + finish):
//   prologue: fold chunk aggregates NC-1 .. c+1 (L2-hot, fixed order)
//   body:     replay recurrence; accumulate actor/critic
//   epilogue: block reduce; last block does final deterministic reduction
// ---------------------------------------------------------------------------
__global__ void __launch_bounds__(BLK)
pass3(const float*  __restrict__ v,
      const float*  __restrict__ rew,
      const float*  __restrict__ nv,
      float*        __restrict__ out)
{
    const int c  = blockIdx.x >> 5;
    const int b  = ((blockIdx.x & 31) << 8) + threadIdx.x;
    const int t1 = c * S + S - 1;

    // ---- prologue: entry carry (right-fold, deterministic fixed order)
    float E = __ldg(&nv[(TT - 1) * BN + b]);
    for (int cc = NC - 1; cc > c; cc--) {
        const float A = g_Ac[cc * BN + b];
        const float B = g_Bc[cc * BN + b];
        E = fmaf(A, E, B);
    }

    // ---- body
    float actor = 0.0f, critic = 0.0f;

    #pragma unroll
    for (int i = 0; i < S; i++) {
        const int t   = t1 - i;
        const int idx = t * BN + b;

        const unsigned u = __float_as_uint(g_ratio[idx]);
        const float  vv = __ldg(&v[idx]);
        const float  rr = __ldg(&rew[idx]);

        const float ratio = __uint_as_float(u & 0x7fffffffu);
        const float g    = (u >> 31) ? 0.0f : GAMMA_F;
        const float rho  = fminf(ratio, 1.0f);
        const float adv  = rho * (rr + g * E - vv);
        critic = fmaf(adv, adv, critic);
        const float cl = fminf(fmaxf(ratio, 0.8f), 1.2f);
        actor += fminf(ratio * adv, cl * adv);
        E = vv + adv;
    }

    // ---- deterministic block reduction
    __shared__ float sa[8], sc[8];
    #pragma unroll
    for (int o = 16; o > 0; o >>= 1) {
        actor  += __shfl_down_sync(0xffffffffu, actor,  o);
        critic += __shfl_down_sync(0xffffffffu, critic, o);
    }
    const int w = threadIdx.x >> 5;
    if ((threadIdx.x & 31) == 0) { sa[w] = actor; sc[w] = critic; }
    __syncthreads();
    if (threadIdx.x == 0) {
        float A = 0.0f, C = 0.0f;
        #pragma unroll
        for (int k = 0; k < 8; k++) { A += sa[k]; C += sc[k]; }
        g_part[blockIdx.x]       = A;
        g_part[GRD + blockIdx.x] = C;
    }

    // ---- last block: final deterministic reduction
    __shared__ bool is_last;
    if (threadIdx.x == 0) {
        __threadfence();
        is_last = (atomicAdd(&g_ctr, 1u) == (unsigned)(GRD - 1));
    }
    __syncthreads();
    if (is_last) {
        const int t = threadIdx.x;
        __shared__ float ra[BLK], rc[BLK];
        float A = 0.0f, C = 0.0f;
        #pragma unroll
        for (int k = 0; k < GRD / BLK; k++) {    // fixed order
            A += g_part[t + k * BLK];
            C += g_part[GRD + t + k * BLK];
        }
        ra[t] = A; rc[t] = C;
        __syncthreads();
        #pragma unroll
        for (int s = BLK / 2; s > 0; s >>= 1) {
            if (t < s) { ra[t] += ra[t + s]; rc[t] += rc[t + s]; }
            __syncthreads();
        }
        if (t == 0) {
            const float inv = 1.0f / (float)NTOT;
            out[0] = (-ra[0] + 0.5f * rc[0]) * inv;   // actor + critic loss
        }
    }
}

extern "C" void kernel_launch(void* const* d_in, const int* in_sizes, int n_in,
                              void* d_out, int out_size)
{
    const float2* prob  = (const float2*)d_in[0];
    const float2* aprob = (const float2*)d_in[1];
    const float*  v     = (const float*)d_in[2];
    const float*  nv    = (const float*)d_in[3];
    const float*  rew   = (const float*)d_in[4];
    const int*    act   = (const int*)d_in[5];
    const int*    dn    = (const int*)d_in[6];
    float* out = (float*)d_out;

    pass1<<<GRD, BLK>>>(prob, aprob, v, rew, act, dn);
    pass3<<<GRD, BLK>>>(v, rew, nv, out);
}